// round 16
// baseline (speedup 1.0000x reference)
#include <cuda_runtime.h>
#include <cuda_bf16.h>
#include <math.h>
#include <stdint.h>

#define BATCH   2
#define LSEQ    4096
#define DMODEL  2048
#define BL      (BATCH * LSEQ)
#define DTRANK  128
#define DSTATE  16
#define OCOLS   160
#define LOG2E   1.4426950408889634f

// ---- scratch ----
__device__ __align__(16) __nv_bfloat16 g_Wx_i [OCOLS * DMODEL];   // integer code k, exact in bf16
__device__ __align__(16) __nv_bfloat16 g_Wdt_i[DMODEL * DTRANK];
__device__ __align__(16) float g_WxSc [OCOLS];                    // per-row scales
__device__ __align__(16) float g_WdtSc[DMODEL];
__device__ __align__(16) __nv_bfloat16 g_xhi [BL * DMODEL];
__device__ __align__(16) __nv_bfloat16 g_xlo [BL * DMODEL];
__device__ __align__(16) __nv_bfloat16 g_xd_hi[BL * DTRANK];
__device__ __align__(16) __nv_bfloat16 g_xd_lo[BL * DTRANK];
__device__ __align__(16) float g_A2 [DMODEL * DSTATE];
__device__ __align__(16) float g_Dq [DMODEL];
__device__ __align__(16) float g_dt [BL * DMODEL];
__device__ __align__(16) float g_uq [BL * DMODEL];
__device__ __align__(16) float g_Braw[BL * DSTATE];
__device__ __align__(16) float g_Craw[BL * DSTATE];
__device__ __align__(16) float g_Bq [BL * DSTATE];
__device__ __align__(16) float g_Cq [BL * DSTATE];
__device__ unsigned g_maxbits[4];   // 0:|x| 1:|dts| 2:|B| 3:|C+prompt|

// ---- helpers ----
__device__ __forceinline__ float ex2f(float x){ float r; asm("ex2.approx.ftz.f32 %0,%1;":"=f"(r):"f"(x)); return r; }
__device__ __forceinline__ float fq_val(float x, float s){
    return fminf(fmaxf(rintf(x / s), -128.0f), 127.0f) * s;
}
__device__ __forceinline__ float block_max(float v){
    __shared__ float red[32];
    __syncthreads();
    #pragma unroll
    for (int o = 16; o; o >>= 1) v = fmaxf(v, __shfl_xor_sync(~0u, v, o));
    int w = threadIdx.x >> 5, nl = threadIdx.x & 31;
    if (nl == 0) red[w] = v;
    __syncthreads();
    int nw = blockDim.x >> 5;
    if (w == 0){
        float m = (nl < nw) ? red[nl] : 0.0f;
        #pragma unroll
        for (int o = 16; o; o >>= 1) m = fmaxf(m, __shfl_xor_sync(~0u, m, o));
        if (nl == 0) red[0] = m;
    }
    __syncthreads();
    return red[0];
}
__device__ __forceinline__ void cp16(void* dst, const void* src){
    unsigned s = (unsigned)__cvta_generic_to_shared(dst);
    asm volatile("cp.async.cg.shared.global [%0], [%1], 16;" :: "r"(s), "l"(src));
}
__device__ __forceinline__ float warp_max(float v){
    #pragma unroll
    for (int o = 16; o; o >>= 1) v = fmaxf(v, __shfl_xor_sync(~0u, v, o));
    return v;
}
__device__ __forceinline__ void ldsm4(unsigned* r, unsigned addr){
    asm volatile("ldmatrix.sync.aligned.m8n8.x4.shared.b16 {%0,%1,%2,%3}, [%4];"
        : "=r"(r[0]), "=r"(r[1]), "=r"(r[2]), "=r"(r[3]) : "r"(addr));
}
__device__ __forceinline__ void mma16816(float* c, const unsigned* a, unsigned b0, unsigned b1){
    asm volatile("mma.sync.aligned.m16n8k16.row.col.f32.bf16.bf16.f32 "
        "{%0,%1,%2,%3}, {%4,%5,%6,%7}, {%8,%9}, {%0,%1,%2,%3};"
        : "+f"(c[0]), "+f"(c[1]), "+f"(c[2]), "+f"(c[3])
        : "r"(a[0]), "r"(a[1]), "r"(a[2]), "r"(a[3]), "r"(b0), "r"(b1));
}
__device__ __forceinline__ unsigned pk2(float a, float b){
    __nv_bfloat162 h = __floats2bfloat162_rn(a, b);
    return *(unsigned*)&h;
}

// ---- prep kernels ----
__global__ void k_init(){ if (threadIdx.x < 4) g_maxbits[threadIdx.x] = 0u; }

// per-row weight quantization: store integer code k (exact bf16) + row scale
template<int W>
__global__ void k_qint(const float* __restrict__ src, int K){
    __nv_bfloat16* dst = W ? g_Wdt_i : g_Wx_i;
    float* scp = W ? g_WdtSc : g_WxSc;
    int row = blockIdx.x;
    const float* s = src + (size_t)row * K;
    float m = 0.0f;
    for (int i = threadIdx.x; i < K; i += blockDim.x) m = fmaxf(m, fabsf(s[i]));
    m = block_max(m);
    float sc = fmaxf(m / 127.0f, 1e-8f);
    if (threadIdx.x == 0) scp[row] = sc;
    for (int i = threadIdx.x; i < K; i += blockDim.x){
        float k = fminf(fmaxf(rintf(s[i] / sc), -128.0f), 127.0f);
        dst[(size_t)row * K + i] = __float2bfloat16(k);   // exact: |k| <= 128
    }
}

__global__ void k_prep_A(const float* __restrict__ A_log){
    int r = blockIdx.x * 8 + (threadIdx.x >> 4), j = threadIdx.x & 15;
    float v = A_log[r * DSTATE + j];
    float m = fabsf(v);
    #pragma unroll
    for (int o = 8; o; o >>= 1) m = fmaxf(m, __shfl_xor_sync(~0u, m, o));
    g_A2[r * DSTATE + j] = -expf(fq_val(v, fmaxf(m / 127.0f, 1e-8f))) * LOG2E;
}

__global__ void k_quant_D(const float* __restrict__ Dskip){
    float m = 0.0f;
    for (int i = threadIdx.x; i < DMODEL; i += blockDim.x) m = fmaxf(m, fabsf(Dskip[i]));
    m = block_max(m);
    float s = fmaxf(m / 127.0f, 1e-8f);
    for (int i = threadIdx.x; i < DMODEL; i += blockDim.x) g_Dq[i] = fq_val(Dskip[i], s);
}

// Fused: abs-max of x AND bf16 hi/lo split (split is scale-independent).
__global__ void k_absmax_split(const float4* __restrict__ x, int n4){
    uint2* oh = (uint2*)g_xhi; uint2* ol = (uint2*)g_xlo;
    float m = 0.0f;
    for (int i = blockIdx.x * blockDim.x + threadIdx.x; i < n4; i += gridDim.x * blockDim.x){
        float4 v = x[i];
        m = fmaxf(m, fmaxf(fmaxf(fabsf(v.x), fabsf(v.y)), fmaxf(fabsf(v.z), fabsf(v.w))));
        __nv_bfloat162 h0 = __floats2bfloat162_rn(v.x, v.y);
        __nv_bfloat162 h1 = __floats2bfloat162_rn(v.z, v.w);
        uint2 hh = { *(unsigned*)&h0, *(unsigned*)&h1 };
        oh[i] = hh;
        __nv_bfloat162 l0 = __floats2bfloat162_rn(v.x - __bfloat162float(h0.x), v.y - __bfloat162float(h0.y));
        __nv_bfloat162 l1 = __floats2bfloat162_rn(v.z - __bfloat162float(h1.x), v.w - __bfloat162float(h1.y));
        uint2 ll = { *(unsigned*)&l0, *(unsigned*)&l1 };
        ol[i] = ll;
    }
    m = block_max(m);
    if (threadIdx.x == 0) atomicMax(&g_maxbits[0], __float_as_uint(m));
}

// u_q = fq(x)
__global__ void k_uq(const float4* __restrict__ x, int n4){
    float s = fmaxf(__uint_as_float(g_maxbits[0]) / 127.0f, 1e-8f);
    float4* o = (float4*)g_uq;
    for (int i = blockIdx.x * blockDim.x + threadIdx.x; i < n4; i += gridDim.x * blockDim.x){
        float4 v = x[i];
        v.x = fq_val(v.x, s); v.y = fq_val(v.y, s);
        v.z = fq_val(v.z, s); v.w = fq_val(v.w, s);
        o[i] = v;
    }
}

__device__ __forceinline__ float softplusf(float x){
    return fmaxf(x, 0.0f) + log1pf(expf(-fabsf(x)));
}
__global__ void k_dt_transform(){
    float s = fmaxf(__uint_as_float(g_maxbits[1]) / 127.0f, 1e-8f);
    float4* p = (float4*)g_dt;
    int n4 = BL * DMODEL / 4;
    for (int i = blockIdx.x * blockDim.x + threadIdx.x; i < n4; i += gridDim.x * blockDim.x){
        float4 v = p[i];
        v.x = softplusf(fq_val(v.x, s)); v.y = softplusf(fq_val(v.y, s));
        v.z = softplusf(fq_val(v.z, s)); v.w = softplusf(fq_val(v.w, s));
        p[i] = v;
    }
}

__global__ void k_quant_BC(){
    int row = blockIdx.x * blockDim.x + threadIdx.x;
    float sB = fmaxf(__uint_as_float(g_maxbits[2]) / 127.0f, 1e-8f);
    float sC = fmaxf(__uint_as_float(g_maxbits[3]) / 127.0f, 1e-8f);
    #pragma unroll
    for (int j = 0; j < DSTATE; j += 4){
        float4 b = *(const float4*)&g_Braw[(size_t)row * DSTATE + j];
        float4 c = *(const float4*)&g_Craw[(size_t)row * DSTATE + j];
        b.x = fq_val(b.x, sB); b.y = fq_val(b.y, sB); b.z = fq_val(b.z, sB); b.w = fq_val(b.w, sB);
        c.x = fq_val(c.x, sC); c.y = fq_val(c.y, sC); c.z = fq_val(c.z, sC); c.w = fq_val(c.w, sC);
        *(float4*)&g_Bq[(size_t)row * DSTATE + j] = b;
        *(float4*)&g_Cq[(size_t)row * DSTATE + j] = c;
    }
}

// ---------------------------------------------------------------------------
// GEMM v4: activation hi/lo split x EXACT integer-code weights (bf16).
// Only 2 MMA passes per accumulator (x_hi*k, x_lo*k); per-row weight scale
// applied in the epilogue.  256 thr / 8 warps, N-split, K-chunk 32.
// ---------------------------------------------------------------------------
template<int N, int KTOT, int MODE>
__global__ __launch_bounds__(256, 1) void k_mma(const float* __restrict__ aux){
    constexpr int NH  = N / 2;
    constexpr int NB2 = NH / 8;
    constexpr int NP2 = NB2 / 2;
    constexpr int NCH = KTOT / 32;
    constexpr int ASZ = 64 * 40;     // bf16 elems per A half
    constexpr int BSZ = N * 40;      // bf16 elems, single weight copy
    constexpr int BUFSZ = 2 * ASZ + BSZ;
    extern __shared__ __nv_bfloat16 sm[];

    int tid = threadIdx.x, wid = tid >> 5, lane = tid & 31;
    int wg = wid >> 2, wil = wid & 3;
    int r0 = blockIdx.x * 64;
    int c0 = MODE ? blockIdx.y * N : 0;
    const __nv_bfloat16* Ah = MODE ? g_xd_hi : g_xhi;
    const __nv_bfloat16* Al = MODE ? g_xd_lo : g_xlo;
    const __nv_bfloat16* Bk = MODE ? g_Wdt_i : g_Wx_i;
    const float* Sc = MODE ? g_WdtSc : g_WxSc;

    float acc[NB2][4];
    #pragma unroll
    for (int n = 0; n < NB2; n++){ acc[n][0]=0.f; acc[n][1]=0.f; acc[n][2]=0.f; acc[n][3]=0.f; }

    auto fill = [&](int c, int buf){
        __nv_bfloat16* base = sm + buf * BUFSZ;
        #pragma unroll
        for (int i = tid; i < 256; i += 256){
            int r = i >> 2, ch = i & 3;
            size_t g = (size_t)(r0 + r) * KTOT + c * 32 + ch * 8;
            unsigned off = r * 40 + ch * 8;
            cp16(base + off, Ah + g);
            cp16(base + ASZ + off, Al + g);
        }
        for (int i = tid; i < N * 4; i += 256){
            int r = i >> 2, ch = i & 3;
            size_t g = (size_t)(c0 + r) * KTOT + c * 32 + ch * 8;
            cp16(base + 2 * ASZ + r * 40 + ch * 8, Bk + g);
        }
        asm volatile("cp.async.commit_group;" ::: "memory");
    };

    fill(0, 0);
    int j = lane >> 3, r8 = lane & 7;
    int lrow = r8 + (j & 1) * 8;
    int lk8  = (j >> 1) * 8;

    for (int c = 0; c < NCH; c++){
        int buf = c & 1;
        if (c + 1 < NCH) fill(c + 1, buf ^ 1);
        if (c + 1 < NCH) asm volatile("cp.async.wait_group 1;" ::: "memory");
        else             asm volatile("cp.async.wait_group 0;" ::: "memory");
        __syncthreads();
        unsigned base = (unsigned)__cvta_generic_to_shared(sm + buf * BUFSZ);
        #pragma unroll
        for (int ks = 0; ks < 2; ks++){
            unsigned ah[4], al[4];
            unsigned aaddr = base + ((wil * 16 + lrow) * 40 + ks * 16 + lk8) * 2;
            ldsm4(ah, aaddr);
            ldsm4(al, aaddr + ASZ * 2);
            #pragma unroll
            for (int p = 0; p < NP2; p++){
                int brow = wg * NH + p * 16 + lrow;
                unsigned baddr = base + (2 * ASZ + brow * 40 + ks * 16 + lk8) * 2;
                unsigned bk4[4];
                ldsm4(bk4, baddr);
                mma16816(acc[2*p],   ah, bk4[0], bk4[2]);
                mma16816(acc[2*p+1], ah, bk4[1], bk4[3]);
                mma16816(acc[2*p],   al, bk4[0], bk4[2]);
                mma16816(acc[2*p+1], al, bk4[1], bk4[3]);
            }
        }
        __syncthreads();
    }

    int g = lane >> 2, tig = lane & 3;
    int row0 = r0 + wil * 16 + g;
    int row1 = row0 + 8;
    if (MODE == 0){
        float mb = 0.f, mc = 0.f;
        #pragma unroll
        for (int n = 0; n < NB2; n++){
            int gcol = wg * NH + n * 8 + tig * 2;
            float s0 = Sc[gcol], s1 = Sc[gcol + 1];
            float a0 = acc[n][0] * s0, a1 = acc[n][1] * s1;
            float a2 = acc[n][2] * s0, a3 = acc[n][3] * s1;
            if (gcol < 128){
                *(unsigned*)&g_xd_hi[(size_t)row0 * DTRANK + gcol] = pk2(a0, a1);
                *(unsigned*)&g_xd_hi[(size_t)row1 * DTRANK + gcol] = pk2(a2, a3);
                float h00 = __bfloat162float(__float2bfloat16(a0));
                float h01 = __bfloat162float(__float2bfloat16(a1));
                float h10 = __bfloat162float(__float2bfloat16(a2));
                float h11 = __bfloat162float(__float2bfloat16(a3));
                *(unsigned*)&g_xd_lo[(size_t)row0 * DTRANK + gcol] = pk2(a0 - h00, a1 - h01);
                *(unsigned*)&g_xd_lo[(size_t)row1 * DTRANK + gcol] = pk2(a2 - h10, a3 - h11);
            } else if (gcol < 144){
                int bc = gcol - 128;
                float2 v0 = { a0, a1 };
                float2 v1 = { a2, a3 };
                *(float2*)&g_Braw[(size_t)row0 * DSTATE + bc] = v0;
                *(float2*)&g_Braw[(size_t)row1 * DSTATE + bc] = v1;
                mb = fmaxf(mb, fmaxf(fmaxf(fabsf(v0.x), fabsf(v0.y)), fmaxf(fabsf(v1.x), fabsf(v1.y))));
            } else {
                int cc = gcol - 144;
                float2 p0 = *(const float2*)&aux[(size_t)row0 * DSTATE + cc];
                float2 p1 = *(const float2*)&aux[(size_t)row1 * DSTATE + cc];
                float2 v0 = { a0 + p0.x, a1 + p0.y };
                float2 v1 = { a2 + p1.x, a3 + p1.y };
                *(float2*)&g_Craw[(size_t)row0 * DSTATE + cc] = v0;
                *(float2*)&g_Craw[(size_t)row1 * DSTATE + cc] = v1;
                mc = fmaxf(mc, fmaxf(fmaxf(fabsf(v0.x), fabsf(v0.y)), fmaxf(fabsf(v1.x), fabsf(v1.y))));
            }
        }
        mb = warp_max(mb); mc = warp_max(mc);
        if (lane == 0 && wg == 1){
            atomicMax(&g_maxbits[2], __float_as_uint(mb));
            atomicMax(&g_maxbits[3], __float_as_uint(mc));
        }
    } else {
        float mx = 0.f;
        #pragma unroll
        for (int n = 0; n < NB2; n++){
            int col = c0 + wg * NH + n * 8 + tig * 2;
            float s0 = Sc[col], s1 = Sc[col + 1];
            float b0v = aux[col], b1v = aux[col + 1];
            float2 v0 = { fmaf(acc[n][0], s0, b0v), fmaf(acc[n][1], s1, b1v) };
            float2 v1 = { fmaf(acc[n][2], s0, b0v), fmaf(acc[n][3], s1, b1v) };
            *(float2*)&g_dt[(size_t)row0 * DMODEL + col] = v0;
            *(float2*)&g_dt[(size_t)row1 * DMODEL + col] = v1;
            mx = fmaxf(mx, fmaxf(fmaxf(fabsf(v0.x), fabsf(v0.y)), fmaxf(fabsf(v1.x), fabsf(v1.y))));
        }
        mx = warp_max(mx);
        if (lane == 0) atomicMax(&g_maxbits[1], __float_as_uint(mx));
    }
}

// ---------------------------------------------------------------------------
// Selective scan v4 (frozen from R14): shuffle-free partial-y reduction.
// ---------------------------------------------------------------------------
#define SCT 64
#define SCC 32
#define SCAN_SMEM_FLOATS 20512

__device__ __forceinline__ void scan_issue(float* sm, int buf, int tid, size_t rowBase, int d0){
    float* sdt = sm + buf * (SCT * SCC);
    float* su  = sm + 4096 + buf * (SCT * SCC);
    float* sB  = sm + 8192 + buf * (SCT * 16);
    float* sC  = sm + 10240 + buf * (SCT * 16);
    #pragma unroll
    for (int i = 0; i < 4; i++){
        int idx = tid + 128 * i;
        int t = idx >> 3, c4 = (idx & 7) << 2;
        size_t g = (rowBase + t) * DMODEL + d0 + c4;
        cp16(&sdt[t * SCC + c4], &g_dt[g]);
        cp16(&su [t * SCC + c4], &g_uq[g]);
    }
    #pragma unroll
    for (int i = 0; i < 2; i++){
        int idx = tid + 128 * i;
        int t = idx >> 2, j4 = (idx & 3) << 2;
        size_t g = (rowBase + t) * DSTATE + j4;
        cp16(&sB[t * 16 + j4], &g_Bq[g]);
        cp16(&sC[t * 16 + j4], &g_Cq[g]);
    }
    asm volatile("cp.async.commit_group;\n" ::: "memory");
}

__device__ __forceinline__ float hsum4(float4 q){
    return (q.x + q.y) + (q.z + q.w);
}

__global__ __launch_bounds__(128, 1) void k_scan(float* __restrict__ out){
    extern __shared__ float smf[];
    float* sy = smf + 12288;
    float* sD = smf + 20480;
    int tid = threadIdx.x;
    int b  = blockIdx.x >> 6;
    int d0 = (blockIdx.x & 63) * SCC;
    int ch = tid >> 2, ln = tid & 3;
    float4 A2r = *(const float4*)&g_A2[(d0 + ch) * DSTATE + ln * 4];
    if (tid < SCC) sD[tid] = g_Dq[d0 + tid];
    float h0 = 0.f, h1 = 0.f, h2 = 0.f, h3 = 0.f;
    size_t batchRow = (size_t)b * LSEQ;
    int syIdx = ch * 4 + ln;

    scan_issue(smf, 0, tid, batchRow, d0);
    for (int tile = 0; tile < LSEQ / SCT; tile++){
        int buf = tile & 1, t0 = tile * SCT;
        if (tile < LSEQ / SCT - 1){
            scan_issue(smf, buf ^ 1, tid, batchRow + t0 + SCT, d0);
            asm volatile("cp.async.wait_group 1;\n" ::: "memory");
        } else {
            asm volatile("cp.async.wait_group 0;\n" ::: "memory");
        }
        __syncthreads();
        const float* dtp = smf + buf * (SCT * SCC);
        const float* up  = smf + 4096 + buf * (SCT * SCC);
        const float* Bp  = smf + 8192 + buf * (SCT * 16);
        const float* Cp  = smf + 10240 + buf * (SCT * 16);
        #pragma unroll 4
        for (int t = 0; t < SCT; t++){
            float dtv = dtp[t * SCC + ch];
            float du  = dtv * up[t * SCC + ch];
            float4 Bv = *(const float4*)&Bp[t * 16 + ln * 4];
            float4 Cv = *(const float4*)&Cp[t * 16 + ln * 4];
            h0 = fmaf(ex2f(dtv * A2r.x), h0, du * Bv.x);
            h1 = fmaf(ex2f(dtv * A2r.y), h1, du * Bv.y);
            h2 = fmaf(ex2f(dtv * A2r.z), h2, du * Bv.z);
            h3 = fmaf(ex2f(dtv * A2r.w), h3, du * Bv.w);
            sy[t * 128 + syIdx] = fmaf(h3, Cv.w, fmaf(h2, Cv.z, fmaf(h1, Cv.y, h0 * Cv.x)));
        }
        __syncthreads();
        #pragma unroll
        for (int i = 0; i < 4; i++){
            int idx = tid + 128 * i;
            int t = idx >> 3, c4 = (idx & 7) << 2;
            const float4* pp = (const float4*)&sy[t * 128 + c4 * 4];
            float4 y = { hsum4(pp[0]), hsum4(pp[1]), hsum4(pp[2]), hsum4(pp[3]) };
            float4 uq = *(const float4*)&up[t * SCC + c4];
            float4 Dv = *(const float4*)&sD[c4];
            y.x = fmaf(uq.x, Dv.x, y.x); y.y = fmaf(uq.y, Dv.y, y.y);
            y.z = fmaf(uq.z, Dv.z, y.z); y.w = fmaf(uq.w, Dv.w, y.w);
            *(float4*)&out[(batchRow + t0 + t) * DMODEL + d0 + c4] = y;
        }
        __syncthreads();
    }
}

// ---------------------------------------------------------------------------
extern "C" void kernel_launch(void* const* d_in, const int* in_sizes, int n_in,
                              void* d_out, int out_size){
    const float* x      = (const float*)d_in[0];
    const float* prompt = (const float*)d_in[1];
    const float* Wx     = (const float*)d_in[2];
    const float* Wdt    = (const float*)d_in[3];
    const float* bdt    = (const float*)d_in[4];
    const float* A_log  = (const float*)d_in[5];
    const float* Dskip  = (const float*)d_in[6];
    float* out = (float*)d_out;

    const int SM1 = (2 * 64 * 40 + 160 * 40) * 2 * 2;   // 46080 B
    const int SM2 = (2 * 64 * 40 + 128 * 40) * 2 * 2;   // 40960 B
    cudaFuncSetAttribute(k_mma<160, 2048, 0>, cudaFuncAttributeMaxDynamicSharedMemorySize, SM1);
    cudaFuncSetAttribute(k_mma<128, 128, 1>,  cudaFuncAttributeMaxDynamicSharedMemorySize, SM2);
    cudaFuncSetAttribute(k_scan, cudaFuncAttributeMaxDynamicSharedMemorySize, SCAN_SMEM_FLOATS * 4);

    int n4x = BL * DMODEL / 4;
    k_init<<<1, 32>>>();                                     // 0
    k_absmax_split<<<1024, 256>>>((const float4*)x, n4x);    // 1
    k_qint<0><<<OCOLS, 128>>>(Wx, DMODEL);                   // 2
    k_mma<160, 2048, 0><<<BL / 64, 256, SM1>>>(prompt);      // 3  <- profiled slot
    k_uq<<<1024, 256>>>((const float4*)x, n4x);              // 4
    k_qint<1><<<DMODEL, 128>>>(Wdt, DTRANK);                 // 5
    k_prep_A<<<DMODEL / 8, 128>>>(A_log);                    // 6
    k_quant_D<<<1, 256>>>(Dskip);                            // 7
    k_quant_BC<<<64, 128>>>();                               // 8
    k_mma<128, 128, 1><<<dim3(BL / 64, DMODEL / 128), 256, SM2>>>(bdt);  // 9
    k_dt_transform<<<2048, 256>>>();                         // 10
    k_scan<<<128, 128, SCAN_SMEM_FLOATS * 4>>>(out);         // 11
}

// round 17
// speedup vs baseline: 1.7702x; 1.7702x over previous
#include <cuda_runtime.h>
#include <cuda_bf16.h>
#include <math.h>
#include <stdint.h>

#define BATCH   2
#define LSEQ    4096
#define DMODEL  2048
#define BL      (BATCH * LSEQ)
#define DTRANK  128
#define DSTATE  16
#define OCOLS   160
#define LOG2E   1.4426950408889634f

// ---- scratch ----
__device__ __align__(16) __nv_bfloat16 g_Wx_hi [OCOLS * DMODEL];
__device__ __align__(16) __nv_bfloat16 g_Wx_lo [OCOLS * DMODEL];
__device__ __align__(16) __nv_bfloat16 g_Wdt_hi[DMODEL * DTRANK];
__device__ __align__(16) __nv_bfloat16 g_Wdt_lo[DMODEL * DTRANK];
__device__ __align__(16) __nv_bfloat16 g_xhi [BL * DMODEL];
__device__ __align__(16) __nv_bfloat16 g_xlo [BL * DMODEL];
__device__ __align__(16) __nv_bfloat16 g_xd_hi[BL * DTRANK];
__device__ __align__(16) __nv_bfloat16 g_xd_lo[BL * DTRANK];
__device__ __align__(16) float g_A2 [DMODEL * DSTATE];
__device__ __align__(16) float g_Dq [DMODEL];
__device__ __align__(16) float g_dt [BL * DMODEL];
__device__ __align__(16) float g_uq [BL * DMODEL];
__device__ __align__(16) float g_Braw[BL * DSTATE];
__device__ __align__(16) float g_Craw[BL * DSTATE];
__device__ __align__(16) float g_Bq [BL * DSTATE];
__device__ __align__(16) float g_Cq [BL * DSTATE];
__device__ unsigned g_maxbits[4];   // 0:|x| 1:|dts| 2:|B| 3:|C+prompt|

// ---- helpers ----
__device__ __forceinline__ float ex2f(float x){ float r; asm("ex2.approx.ftz.f32 %0,%1;":"=f"(r):"f"(x)); return r; }
__device__ __forceinline__ float fq_val(float x, float s){
    return fminf(fmaxf(rintf(x / s), -128.0f), 127.0f) * s;
}
__device__ __forceinline__ float block_max(float v){
    __shared__ float red[32];
    __syncthreads();
    #pragma unroll
    for (int o = 16; o; o >>= 1) v = fmaxf(v, __shfl_xor_sync(~0u, v, o));
    int w = threadIdx.x >> 5, nl = threadIdx.x & 31;
    if (nl == 0) red[w] = v;
    __syncthreads();
    int nw = blockDim.x >> 5;
    if (w == 0){
        float m = (nl < nw) ? red[nl] : 0.0f;
        #pragma unroll
        for (int o = 16; o; o >>= 1) m = fmaxf(m, __shfl_xor_sync(~0u, m, o));
        if (nl == 0) red[0] = m;
    }
    __syncthreads();
    return red[0];
}
__device__ __forceinline__ void cp16(void* dst, const void* src){
    unsigned s = (unsigned)__cvta_generic_to_shared(dst);
    asm volatile("cp.async.cg.shared.global [%0], [%1], 16;" :: "r"(s), "l"(src));
}
__device__ __forceinline__ float warp_max(float v){
    #pragma unroll
    for (int o = 16; o; o >>= 1) v = fmaxf(v, __shfl_xor_sync(~0u, v, o));
    return v;
}
__device__ __forceinline__ void ldsm4(unsigned* r, unsigned addr){
    asm volatile("ldmatrix.sync.aligned.m8n8.x4.shared.b16 {%0,%1,%2,%3}, [%4];"
        : "=r"(r[0]), "=r"(r[1]), "=r"(r[2]), "=r"(r[3]) : "r"(addr));
}
__device__ __forceinline__ void mma16816(float* c, const unsigned* a, unsigned b0, unsigned b1){
    asm volatile("mma.sync.aligned.m16n8k16.row.col.f32.bf16.bf16.f32 "
        "{%0,%1,%2,%3}, {%4,%5,%6,%7}, {%8,%9}, {%0,%1,%2,%3};"
        : "+f"(c[0]), "+f"(c[1]), "+f"(c[2]), "+f"(c[3])
        : "r"(a[0]), "r"(a[1]), "r"(a[2]), "r"(a[3]), "r"(b0), "r"(b1));
}
__device__ __forceinline__ unsigned pk2(float a, float b){
    __nv_bfloat162 h = __floats2bfloat162_rn(a, b);
    return *(unsigned*)&h;
}

// ---- prep kernels ----
__global__ void k_init(){ if (threadIdx.x < 4) g_maxbits[threadIdx.x] = 0u; }

template<int W>
__global__ void k_qsplit(const float* __restrict__ src, int K){
    __nv_bfloat16* hi = W ? g_Wdt_hi : g_Wx_hi;
    __nv_bfloat16* lo = W ? g_Wdt_lo : g_Wx_lo;
    int row = blockIdx.x;
    const float* s = src + (size_t)row * K;
    float m = 0.0f;
    for (int i = threadIdx.x; i < K; i += blockDim.x) m = fmaxf(m, fabsf(s[i]));
    m = block_max(m);
    float sc = fmaxf(m / 127.0f, 1e-8f);
    for (int i = threadIdx.x; i < K; i += blockDim.x){
        float q = fq_val(s[i], sc);
        __nv_bfloat16 h = __float2bfloat16(q);
        hi[(size_t)row * K + i] = h;
        lo[(size_t)row * K + i] = __float2bfloat16(q - __bfloat162float(h));
    }
}

__global__ void k_prep_A(const float* __restrict__ A_log){
    int r = blockIdx.x * 8 + (threadIdx.x >> 4), j = threadIdx.x & 15;
    float v = A_log[r * DSTATE + j];
    float m = fabsf(v);
    #pragma unroll
    for (int o = 8; o; o >>= 1) m = fmaxf(m, __shfl_xor_sync(~0u, m, o));
    g_A2[r * DSTATE + j] = -expf(fq_val(v, fmaxf(m / 127.0f, 1e-8f))) * LOG2E;
}

__global__ void k_quant_D(const float* __restrict__ Dskip){
    float m = 0.0f;
    for (int i = threadIdx.x; i < DMODEL; i += blockDim.x) m = fmaxf(m, fabsf(Dskip[i]));
    m = block_max(m);
    float s = fmaxf(m / 127.0f, 1e-8f);
    for (int i = threadIdx.x; i < DMODEL; i += blockDim.x) g_Dq[i] = fq_val(Dskip[i], s);
}

// Fused: abs-max of x AND bf16 hi/lo split (split is scale-independent).
__global__ void k_absmax_split(const float4* __restrict__ x, int n4){
    uint2* oh = (uint2*)g_xhi; uint2* ol = (uint2*)g_xlo;
    float m = 0.0f;
    for (int i = blockIdx.x * blockDim.x + threadIdx.x; i < n4; i += gridDim.x * blockDim.x){
        float4 v = x[i];
        m = fmaxf(m, fmaxf(fmaxf(fabsf(v.x), fabsf(v.y)), fmaxf(fabsf(v.z), fabsf(v.w))));
        __nv_bfloat162 h0 = __floats2bfloat162_rn(v.x, v.y);
        __nv_bfloat162 h1 = __floats2bfloat162_rn(v.z, v.w);
        uint2 hh = { *(unsigned*)&h0, *(unsigned*)&h1 };
        oh[i] = hh;
        __nv_bfloat162 l0 = __floats2bfloat162_rn(v.x - __bfloat162float(h0.x), v.y - __bfloat162float(h0.y));
        __nv_bfloat162 l1 = __floats2bfloat162_rn(v.z - __bfloat162float(h1.x), v.w - __bfloat162float(h1.y));
        uint2 ll = { *(unsigned*)&l0, *(unsigned*)&l1 };
        ol[i] = ll;
    }
    m = block_max(m);
    if (threadIdx.x == 0) atomicMax(&g_maxbits[0], __float_as_uint(m));
}

// u_q = fq(x)
__global__ void k_uq(const float4* __restrict__ x, int n4){
    float s = fmaxf(__uint_as_float(g_maxbits[0]) / 127.0f, 1e-8f);
    float4* o = (float4*)g_uq;
    for (int i = blockIdx.x * blockDim.x + threadIdx.x; i < n4; i += gridDim.x * blockDim.x){
        float4 v = x[i];
        v.x = fq_val(v.x, s); v.y = fq_val(v.y, s);
        v.z = fq_val(v.z, s); v.w = fq_val(v.w, s);
        o[i] = v;
    }
}

__device__ __forceinline__ float softplusf(float x){
    return fmaxf(x, 0.0f) + log1pf(expf(-fabsf(x)));
}
__global__ void k_dt_transform(){
    float s = fmaxf(__uint_as_float(g_maxbits[1]) / 127.0f, 1e-8f);
    float4* p = (float4*)g_dt;
    int n4 = BL * DMODEL / 4;
    for (int i = blockIdx.x * blockDim.x + threadIdx.x; i < n4; i += gridDim.x * blockDim.x){
        float4 v = p[i];
        v.x = softplusf(fq_val(v.x, s)); v.y = softplusf(fq_val(v.y, s));
        v.z = softplusf(fq_val(v.z, s)); v.w = softplusf(fq_val(v.w, s));
        p[i] = v;
    }
}

__global__ void k_quant_BC(){
    int row = blockIdx.x * blockDim.x + threadIdx.x;
    float sB = fmaxf(__uint_as_float(g_maxbits[2]) / 127.0f, 1e-8f);
    float sC = fmaxf(__uint_as_float(g_maxbits[3]) / 127.0f, 1e-8f);
    #pragma unroll
    for (int j = 0; j < DSTATE; j += 4){
        float4 b = *(const float4*)&g_Braw[(size_t)row * DSTATE + j];
        float4 c = *(const float4*)&g_Craw[(size_t)row * DSTATE + j];
        b.x = fq_val(b.x, sB); b.y = fq_val(b.y, sB); b.z = fq_val(b.z, sB); b.w = fq_val(b.w, sB);
        c.x = fq_val(c.x, sC); c.y = fq_val(c.y, sC); c.z = fq_val(c.z, sC); c.w = fq_val(c.w, sC);
        *(float4*)&g_Bq[(size_t)row * DSTATE + j] = b;
        *(float4*)&g_Cq[(size_t)row * DSTATE + j] = c;
    }
}

// ---------------------------------------------------------------------------
// bf16 hi/lo split GEMM via mma.sync.m16n8k16 (R14 numerics, templated KCHUNK).
// 256 thr / 8 warps, N-split. GEMM1 uses KCHUNK=64 (half the barrier/wait
// cadence; grid-limited to 1 CTA/SM so the smem growth is free). GEMM2 keeps
// KCHUNK=32 to preserve its multi-CTA/SM occupancy.
// ---------------------------------------------------------------------------
template<int N, int KTOT, int MODE, int KCHUNK>
__global__ __launch_bounds__(256, 1) void k_mma(const float* __restrict__ aux){
    constexpr int NH  = N / 2;
    constexpr int NB2 = NH / 8;
    constexpr int NP2 = NB2 / 2;
    constexpr int NCH = KTOT / KCHUNK;
    constexpr int KS  = KCHUNK / 16;       // ks steps per chunk
    constexpr int QC  = KCHUNK / 8;        // 16B quads per row
    constexpr int ROWW = KCHUNK + 8;       // row pitch (bf16 elems)
    constexpr int ASZ = 64 * ROWW;
    constexpr int BSZ = N * ROWW;
    constexpr int BUFSZ = 2 * ASZ + 2 * BSZ;
    extern __shared__ __nv_bfloat16 sm[];

    int tid = threadIdx.x, wid = tid >> 5, lane = tid & 31;
    int wg = wid >> 2, wil = wid & 3;
    int r0 = blockIdx.x * 64;
    int c0 = MODE ? blockIdx.y * N : 0;
    const __nv_bfloat16* Ah = MODE ? g_xd_hi : g_xhi;
    const __nv_bfloat16* Al = MODE ? g_xd_lo : g_xlo;
    const __nv_bfloat16* Bh = MODE ? g_Wdt_hi : g_Wx_hi;
    const __nv_bfloat16* Bl = MODE ? g_Wdt_lo : g_Wx_lo;

    float acc[NB2][4];
    #pragma unroll
    for (int n = 0; n < NB2; n++){ acc[n][0]=0.f; acc[n][1]=0.f; acc[n][2]=0.f; acc[n][3]=0.f; }

    auto fill = [&](int c, int buf){
        __nv_bfloat16* base = sm + buf * BUFSZ;
        #pragma unroll
        for (int i = tid; i < 64 * QC; i += 256){
            int r = i / QC, ch = i % QC;
            size_t g = (size_t)(r0 + r) * KTOT + c * KCHUNK + ch * 8;
            unsigned off = r * ROWW + ch * 8;
            cp16(base + off, Ah + g);
            cp16(base + ASZ + off, Al + g);
        }
        for (int i = tid; i < N * QC; i += 256){
            int r = i / QC, ch = i % QC;
            size_t g = (size_t)(c0 + r) * KTOT + c * KCHUNK + ch * 8;
            unsigned off = r * ROWW + ch * 8;
            cp16(base + 2 * ASZ + off, Bh + g);
            cp16(base + 2 * ASZ + BSZ + off, Bl + g);
        }
        asm volatile("cp.async.commit_group;" ::: "memory");
    };

    fill(0, 0);
    int j = lane >> 3, r8 = lane & 7;
    int lrow = r8 + (j & 1) * 8;
    int lk8  = (j >> 1) * 8;

    for (int c = 0; c < NCH; c++){
        int buf = c & 1;
        if (c + 1 < NCH) fill(c + 1, buf ^ 1);
        if (c + 1 < NCH) asm volatile("cp.async.wait_group 1;" ::: "memory");
        else             asm volatile("cp.async.wait_group 0;" ::: "memory");
        __syncthreads();
        unsigned base = (unsigned)__cvta_generic_to_shared(sm + buf * BUFSZ);
        #pragma unroll
        for (int ks = 0; ks < KS; ks++){
            unsigned ah[4], al[4];
            unsigned aaddr = base + ((wil * 16 + lrow) * ROWW + ks * 16 + lk8) * 2;
            ldsm4(ah, aaddr);
            ldsm4(al, aaddr + ASZ * 2);
            #pragma unroll
            for (int p = 0; p < NP2; p++){
                int brow = wg * NH + p * 16 + lrow;
                unsigned baddr = base + (2 * ASZ + brow * ROWW + ks * 16 + lk8) * 2;
                unsigned bh4[4], bl4[4];
                ldsm4(bh4, baddr);
                ldsm4(bl4, baddr + BSZ * 2);
                mma16816(acc[2*p],   ah, bh4[0], bh4[2]);
                mma16816(acc[2*p+1], ah, bh4[1], bh4[3]);
                mma16816(acc[2*p],   ah, bl4[0], bl4[2]);
                mma16816(acc[2*p+1], ah, bl4[1], bl4[3]);
                mma16816(acc[2*p],   al, bh4[0], bh4[2]);
                mma16816(acc[2*p+1], al, bh4[1], bh4[3]);
            }
        }
        __syncthreads();
    }

    int g = lane >> 2, tig = lane & 3;
    int row0 = r0 + wil * 16 + g;
    int row1 = row0 + 8;
    if (MODE == 0){
        float mb = 0.f, mc = 0.f;
        #pragma unroll
        for (int n = 0; n < NB2; n++){
            int gcol = wg * NH + n * 8 + tig * 2;
            if (gcol < 128){
                *(unsigned*)&g_xd_hi[(size_t)row0 * DTRANK + gcol] = pk2(acc[n][0], acc[n][1]);
                *(unsigned*)&g_xd_hi[(size_t)row1 * DTRANK + gcol] = pk2(acc[n][2], acc[n][3]);
                float h00 = __bfloat162float(__float2bfloat16(acc[n][0]));
                float h01 = __bfloat162float(__float2bfloat16(acc[n][1]));
                float h10 = __bfloat162float(__float2bfloat16(acc[n][2]));
                float h11 = __bfloat162float(__float2bfloat16(acc[n][3]));
                *(unsigned*)&g_xd_lo[(size_t)row0 * DTRANK + gcol] = pk2(acc[n][0] - h00, acc[n][1] - h01);
                *(unsigned*)&g_xd_lo[(size_t)row1 * DTRANK + gcol] = pk2(acc[n][2] - h10, acc[n][3] - h11);
            } else if (gcol < 144){
                int bc = gcol - 128;
                float2 v0 = { acc[n][0], acc[n][1] };
                float2 v1 = { acc[n][2], acc[n][3] };
                *(float2*)&g_Braw[(size_t)row0 * DSTATE + bc] = v0;
                *(float2*)&g_Braw[(size_t)row1 * DSTATE + bc] = v1;
                mb = fmaxf(mb, fmaxf(fmaxf(fabsf(v0.x), fabsf(v0.y)), fmaxf(fabsf(v1.x), fabsf(v1.y))));
            } else {
                int cc = gcol - 144;
                float2 p0 = *(const float2*)&aux[(size_t)row0 * DSTATE + cc];
                float2 p1 = *(const float2*)&aux[(size_t)row1 * DSTATE + cc];
                float2 v0 = { acc[n][0] + p0.x, acc[n][1] + p0.y };
                float2 v1 = { acc[n][2] + p1.x, acc[n][3] + p1.y };
                *(float2*)&g_Craw[(size_t)row0 * DSTATE + cc] = v0;
                *(float2*)&g_Craw[(size_t)row1 * DSTATE + cc] = v1;
                mc = fmaxf(mc, fmaxf(fmaxf(fabsf(v0.x), fabsf(v0.y)), fmaxf(fabsf(v1.x), fabsf(v1.y))));
            }
        }
        mb = warp_max(mb); mc = warp_max(mc);
        if (lane == 0 && wg == 1){
            atomicMax(&g_maxbits[2], __float_as_uint(mb));
            atomicMax(&g_maxbits[3], __float_as_uint(mc));
        }
    } else {
        float mx = 0.f;
        #pragma unroll
        for (int n = 0; n < NB2; n++){
            int col = c0 + wg * NH + n * 8 + tig * 2;
            float b0v = aux[col], b1v = aux[col + 1];
            float2 v0 = { acc[n][0] + b0v, acc[n][1] + b1v };
            float2 v1 = { acc[n][2] + b0v, acc[n][3] + b1v };
            *(float2*)&g_dt[(size_t)row0 * DMODEL + col] = v0;
            *(float2*)&g_dt[(size_t)row1 * DMODEL + col] = v1;
            mx = fmaxf(mx, fmaxf(fmaxf(fabsf(v0.x), fabsf(v0.y)), fmaxf(fabsf(v1.x), fabsf(v1.y))));
        }
        mx = warp_max(mx);
        if (lane == 0) atomicMax(&g_maxbits[1], __float_as_uint(mx));
    }
}

// ---------------------------------------------------------------------------
// Selective scan v5: R14's shuffle-free scan + one-step register prefetch
// rotation (same ops, same order — hides LDS latency only).
// ---------------------------------------------------------------------------
#define SCT 64
#define SCC 32
#define SCAN_SMEM_FLOATS 20512

__device__ __forceinline__ void scan_issue(float* sm, int buf, int tid, size_t rowBase, int d0){
    float* sdt = sm + buf * (SCT * SCC);
    float* su  = sm + 4096 + buf * (SCT * SCC);
    float* sB  = sm + 8192 + buf * (SCT * 16);
    float* sC  = sm + 10240 + buf * (SCT * 16);
    #pragma unroll
    for (int i = 0; i < 4; i++){
        int idx = tid + 128 * i;
        int t = idx >> 3, c4 = (idx & 7) << 2;
        size_t g = (rowBase + t) * DMODEL + d0 + c4;
        cp16(&sdt[t * SCC + c4], &g_dt[g]);
        cp16(&su [t * SCC + c4], &g_uq[g]);
    }
    #pragma unroll
    for (int i = 0; i < 2; i++){
        int idx = tid + 128 * i;
        int t = idx >> 2, j4 = (idx & 3) << 2;
        size_t g = (rowBase + t) * DSTATE + j4;
        cp16(&sB[t * 16 + j4], &g_Bq[g]);
        cp16(&sC[t * 16 + j4], &g_Cq[g]);
    }
    asm volatile("cp.async.commit_group;\n" ::: "memory");
}

__device__ __forceinline__ float hsum4(float4 q){
    return (q.x + q.y) + (q.z + q.w);
}

__global__ __launch_bounds__(128, 1) void k_scan(float* __restrict__ out){
    extern __shared__ float smf[];
    float* sy = smf + 12288;
    float* sD = smf + 20480;
    int tid = threadIdx.x;
    int b  = blockIdx.x >> 6;
    int d0 = (blockIdx.x & 63) * SCC;
    int ch = tid >> 2, ln = tid & 3;
    float4 A2r = *(const float4*)&g_A2[(d0 + ch) * DSTATE + ln * 4];
    if (tid < SCC) sD[tid] = g_Dq[d0 + tid];
    float h0 = 0.f, h1 = 0.f, h2 = 0.f, h3 = 0.f;
    size_t batchRow = (size_t)b * LSEQ;
    int syIdx = ch * 4 + ln;

    scan_issue(smf, 0, tid, batchRow, d0);
    for (int tile = 0; tile < LSEQ / SCT; tile++){
        int buf = tile & 1, t0 = tile * SCT;
        if (tile < LSEQ / SCT - 1){
            scan_issue(smf, buf ^ 1, tid, batchRow + t0 + SCT, d0);
            asm volatile("cp.async.wait_group 1;\n" ::: "memory");
        } else {
            asm volatile("cp.async.wait_group 0;\n" ::: "memory");
        }
        __syncthreads();
        const float* dtp = smf + buf * (SCT * SCC);
        const float* up  = smf + 4096 + buf * (SCT * SCC);
        const float* Bp  = smf + 8192 + buf * (SCT * 16);
        const float* Cp  = smf + 10240 + buf * (SCT * 16);

        // prime step-0 operands
        float dtv = dtp[ch];
        float uqv = up[ch];
        float4 Bv = *(const float4*)&Bp[ln * 4];
        float4 Cv = *(const float4*)&Cp[ln * 4];

        #pragma unroll 4
        for (int t = 0; t < SCT; t++){
            int tn = (t + 1) & (SCT - 1);          // wrap: last prefetch unused
            float dtv_n = dtp[tn * SCC + ch];
            float uq_n  = up [tn * SCC + ch];
            float4 Bv_n = *(const float4*)&Bp[tn * 16 + ln * 4];
            float4 Cv_n = *(const float4*)&Cp[tn * 16 + ln * 4];

            float du = dtv * uqv;
            h0 = fmaf(ex2f(dtv * A2r.x), h0, du * Bv.x);
            h1 = fmaf(ex2f(dtv * A2r.y), h1, du * Bv.y);
            h2 = fmaf(ex2f(dtv * A2r.z), h2, du * Bv.z);
            h3 = fmaf(ex2f(dtv * A2r.w), h3, du * Bv.w);
            sy[t * 128 + syIdx] = fmaf(h3, Cv.w, fmaf(h2, Cv.z, fmaf(h1, Cv.y, h0 * Cv.x)));

            dtv = dtv_n; uqv = uq_n; Bv = Bv_n; Cv = Cv_n;
        }
        __syncthreads();
        #pragma unroll
        for (int i = 0; i < 4; i++){
            int idx = tid + 128 * i;
            int t = idx >> 3, c4 = (idx & 7) << 2;
            const float4* pp = (const float4*)&sy[t * 128 + c4 * 4];
            float4 y = { hsum4(pp[0]), hsum4(pp[1]), hsum4(pp[2]), hsum4(pp[3]) };
            float4 uq = *(const float4*)&up[t * SCC + c4];
            float4 Dv = *(const float4*)&sD[c4];
            y.x = fmaf(uq.x, Dv.x, y.x); y.y = fmaf(uq.y, Dv.y, y.y);
            y.z = fmaf(uq.z, Dv.z, y.z); y.w = fmaf(uq.w, Dv.w, y.w);
            *(float4*)&out[(batchRow + t0 + t) * DMODEL + d0 + c4] = y;
        }
        __syncthreads();
    }
}

// ---------------------------------------------------------------------------
extern "C" void kernel_launch(void* const* d_in, const int* in_sizes, int n_in,
                              void* d_out, int out_size){
    const float* x      = (const float*)d_in[0];
    const float* prompt = (const float*)d_in[1];
    const float* Wx     = (const float*)d_in[2];
    const float* Wdt    = (const float*)d_in[3];
    const float* bdt    = (const float*)d_in[4];
    const float* A_log  = (const float*)d_in[5];
    const float* Dskip  = (const float*)d_in[6];
    float* out = (float*)d_out;

    // GEMM1: KCHUNK=64 -> BUFSZ = 2*(64*72) + 2*(160*72) elems; x2 bufs x2 B
    const int SM1 = 2 * (2 * 64 * 72 + 2 * 160 * 72) * 2;   // 129024 B
    // GEMM2: KCHUNK=32 (unchanged from R14)
    const int SM2 = 2 * (2 * 64 * 40 + 2 * 128 * 40) * 2;   // 61440 B
    cudaFuncSetAttribute(k_mma<160, 2048, 0, 64>, cudaFuncAttributeMaxDynamicSharedMemorySize, SM1);
    cudaFuncSetAttribute(k_mma<128, 128, 1, 32>,  cudaFuncAttributeMaxDynamicSharedMemorySize, SM2);
    cudaFuncSetAttribute(k_scan, cudaFuncAttributeMaxDynamicSharedMemorySize, SCAN_SMEM_FLOATS * 4);

    int n4x = BL * DMODEL / 4;
    k_init<<<1, 32>>>();                                     // 0
    k_absmax_split<<<1024, 256>>>((const float4*)x, n4x);    // 1
    k_qsplit<0><<<OCOLS, 128>>>(Wx, DMODEL);                 // 2
    k_mma<160, 2048, 0, 64><<<BL / 64, 256, SM1>>>(prompt);  // 3  <- profiled slot
    k_uq<<<1024, 256>>>((const float4*)x, n4x);              // 4
    k_qsplit<1><<<DMODEL, 128>>>(Wdt, DTRANK);               // 5
    k_prep_A<<<DMODEL / 8, 128>>>(A_log);                    // 6
    k_quant_D<<<1, 256>>>(Dskip);                            // 7
    k_quant_BC<<<64, 128>>>();                               // 8
    k_mma<128, 128, 1, 32><<<dim3(BL / 64, DMODEL / 128), 256, SM2>>>(bdt);  // 9
    k_dt_transform<<<2048, 256>>>();                         // 10
    k_scan<<<128, 128, SCAN_SMEM_FLOATS * 4>>>(out);         // 11
}